// round 3
// baseline (speedup 1.0000x reference)
#include <cuda_runtime.h>
#include <cstdint>

#define N_NODES 50000
#define N_EDGES 1600000
#define IN_DIM  256
#define OUT_DIM 128
#define T_STEPS 8

// Scratch (device globals — no allocation allowed). float4 typed => 16B aligned.
__device__ __align__(16) float4 g_h4[N_NODES * OUT_DIM / 4];     // h = x @ W
__device__ __align__(16) float4 g_agg4[N_NODES * OUT_DIM / 4];   // GCN aggregation
__device__ float g_dinv[N_NODES];
__device__ int   g_deg[N_NODES];

// ---------------------------------------------------------------------------
// Degree: deg[n] = 1 (self loop) + #edges with dst == n
// NOTE: edge_index is int32 on device (JAX x64 disabled downgrades int64).
// ---------------------------------------------------------------------------
__global__ void k_deg_init() {
    int n = blockIdx.x * blockDim.x + threadIdx.x;
    if (n < N_NODES) g_deg[n] = 1;
}

__global__ void k_deg_count(const int* __restrict__ ei) {
    int e = blockIdx.x * blockDim.x + threadIdx.x;
    if (e < N_EDGES) {
        int dst = ei[N_EDGES + e];
        atomicAdd(&g_deg[dst], 1);
    }
}

__global__ void k_dinv() {
    int n = blockIdx.x * blockDim.x + threadIdx.x;
    if (n < N_NODES) g_dinv[n] = rsqrtf((float)g_deg[n]);
}

// ---------------------------------------------------------------------------
// SGEMM: h = x @ W, and init agg = h * dinv^2 (self-loop contribution)
// BM=128, BN=128(=OUT), BK=32, 256 threads, 8x8 microtile
// ---------------------------------------------------------------------------
__global__ __launch_bounds__(256) void k_gemm(const float* __restrict__ x,
                                              const float* __restrict__ W) {
    __shared__ float As[32][128];   // [k][m]  (x tile transposed)
    __shared__ float Bs[32][128];   // [k][n]

    const int tid = threadIdx.x;
    const int block_row = blockIdx.x * 128;
    const int tx = tid % 16;        // output col group (16 * 8 = 128 cols)
    const int ty = tid / 16;        // output row group (16 * 8 = 128 rows)

    float acc[8][8];
#pragma unroll
    for (int i = 0; i < 8; i++)
#pragma unroll
        for (int j = 0; j < 8; j++) acc[i][j] = 0.0f;

    const int aRow = tid / 8;          // 0..31
    const int aCol = (tid % 8) * 4;    // 0,4,..,28
    const int bRow = tid / 32;         // 0..7
    const int bCol = (tid % 32) * 4;   // 0,4,..,124

    for (int k0 = 0; k0 < IN_DIM; k0 += 32) {
        // x tile: 128 rows x 32 k, stored transposed into As[k][m]
#pragma unroll
        for (int p = 0; p < 4; p++) {
            int m = aRow + p * 32;
            int gm = block_row + m;
            float4 v = make_float4(0.f, 0.f, 0.f, 0.f);
            if (gm < N_NODES)
                v = *(const float4*)&x[(size_t)gm * IN_DIM + k0 + aCol];
            As[aCol + 0][m] = v.x;
            As[aCol + 1][m] = v.y;
            As[aCol + 2][m] = v.z;
            As[aCol + 3][m] = v.w;
        }
        // W tile: 32 k x 128 n
#pragma unroll
        for (int p = 0; p < 4; p++) {
            int k = bRow + p * 8;
            float4 v = *(const float4*)&W[(size_t)(k0 + k) * OUT_DIM + bCol];
            *(float4*)&Bs[k][bCol] = v;
        }
        __syncthreads();

#pragma unroll
        for (int kk = 0; kk < 32; kk++) {
            float ra[8], rb[8];
#pragma unroll
            for (int i = 0; i < 8; i++) ra[i] = As[kk][ty * 8 + i];
#pragma unroll
            for (int j = 0; j < 8; j++) rb[j] = Bs[kk][tx * 8 + j];
#pragma unroll
            for (int i = 0; i < 8; i++)
#pragma unroll
                for (int j = 0; j < 8; j++)
                    acc[i][j] = fmaf(ra[i], rb[j], acc[i][j]);
        }
        __syncthreads();
    }

#pragma unroll
    for (int i = 0; i < 8; i++) {
        int gm = block_row + ty * 8 + i;
        if (gm >= N_NODES) break;
        float di = g_dinv[gm];
        float di2 = di * di;
#pragma unroll
        for (int j = 0; j < 8; j += 4) {
            float4 hv = make_float4(acc[i][j], acc[i][j + 1], acc[i][j + 2], acc[i][j + 3]);
            int vidx = gm * (OUT_DIM / 4) + (tx * 8 + j) / 4;
            g_h4[vidx] = hv;
            g_agg4[vidx] = make_float4(hv.x * di2, hv.y * di2, hv.z * di2, hv.w * di2);
        }
    }
}

// ---------------------------------------------------------------------------
// Edge scatter: agg[dst] += h[src] * dinv[src]*dinv[dst]
// One warp per edge; 32 lanes cover 32 float4 = 128 floats; vector red to L2.
// ---------------------------------------------------------------------------
__global__ __launch_bounds__(256) void k_scatter(const int* __restrict__ ei) {
    int w = (blockIdx.x * 256 + threadIdx.x) >> 5;   // edge id
    int lane = threadIdx.x & 31;
    if (w >= N_EDGES) return;

    int src = ei[w];
    int dst = ei[N_EDGES + w];
    float norm = g_dinv[src] * g_dinv[dst];

    float4 v = g_h4[src * (OUT_DIM / 4) + lane];
    float4* ap = &g_agg4[dst * (OUT_DIM / 4) + lane];

    asm volatile("red.global.add.v4.f32 [%0], {%1,%2,%3,%4};"
                 :: "l"(ap),
                    "f"(v.x * norm), "f"(v.y * norm), "f"(v.z * norm), "f"(v.w * norm)
                 : "memory");
}

// ---------------------------------------------------------------------------
// Spiking scan: u = 0.1*agg, z0 = 0; T=8 steps
//   Hm = z + (u - z)/2 ; o = (Hm>=1) ; z = Hm - o
// out layout: o_seq [8, N, 128] then z_seq [8, N, 128]
// ---------------------------------------------------------------------------
__global__ __launch_bounds__(256) void k_scan(float4* __restrict__ out) {
    const int VEC = N_NODES * OUT_DIM / 4;   // 1,600,000 float4
    int i = blockIdx.x * blockDim.x + threadIdx.x;
    if (i >= VEC) return;

    float4 a = g_agg4[i];
    float4 u = make_float4(a.x * 0.1f, a.y * 0.1f, a.z * 0.1f, a.w * 0.1f);
    float4 z = make_float4(0.f, 0.f, 0.f, 0.f);

#pragma unroll
    for (int t = 0; t < T_STEPS; t++) {
        float4 Hm = make_float4(z.x + (u.x - z.x) * 0.5f,
                                z.y + (u.y - z.y) * 0.5f,
                                z.z + (u.z - z.z) * 0.5f,
                                z.w + (u.w - z.w) * 0.5f);
        float4 o = make_float4(Hm.x >= 1.0f ? 1.f : 0.f,
                               Hm.y >= 1.0f ? 1.f : 0.f,
                               Hm.z >= 1.0f ? 1.f : 0.f,
                               Hm.w >= 1.0f ? 1.f : 0.f);
        z = make_float4(Hm.x - o.x, Hm.y - o.y, Hm.z - o.z, Hm.w - o.w);
        out[(size_t)t * VEC + i] = o;
        out[(size_t)(T_STEPS + t) * VEC + i] = z;
    }
}

// ---------------------------------------------------------------------------
extern "C" void kernel_launch(void* const* d_in, const int* in_sizes, int n_in,
                              void* d_out, int out_size) {
    const float* x = (const float*)d_in[0];
    const float* W = (const float*)d_in[1];
    const int* ei = (const int*)d_in[2];
    float4* out = (float4*)d_out;

    k_deg_init<<<(N_NODES + 255) / 256, 256>>>();
    k_deg_count<<<(N_EDGES + 255) / 256, 256>>>(ei);
    k_dinv<<<(N_NODES + 255) / 256, 256>>>();
    k_gemm<<<(N_NODES + 127) / 128, 256>>>(x, W);
    k_scatter<<<N_EDGES / 8, 256>>>(ei);   // 1.6M warps, 8 warps/block
    k_scan<<<(N_NODES * OUT_DIM / 4 + 255) / 256, 256>>>(out);
}

// round 4
// speedup vs baseline: 1.0967x; 1.0967x over previous
#include <cuda_runtime.h>
#include <cstdint>

#define N_NODES 50000
#define N_EDGES 1600000
#define IN_DIM  256
#define OUT_DIM 128
#define T_STEPS 8

// Scratch (device globals — no allocation allowed)
__device__ __align__(16) float4 g_h4[N_NODES * OUT_DIM / 4];  // h = x @ W
__device__ float g_dinv[N_NODES];
__device__ int   g_cnt[N_NODES];        // in-edge count (no self loop)
__device__ int   g_off[N_NODES + 1];    // CSR offsets by dst
__device__ int   g_cursor[N_NODES];     // scatter cursors
__device__ int   g_srcs[N_EDGES];       // CSR column (src) indices

// ---------------------------------------------------------------------------
__global__ void k_zero_cnt() {
    int n = blockIdx.x * blockDim.x + threadIdx.x;
    if (n < N_NODES) g_cnt[n] = 0;
}

__global__ void k_hist(const int* __restrict__ ei) {
    int e = blockIdx.x * blockDim.x + threadIdx.x;
    if (e < N_EDGES) atomicAdd(&g_cnt[ei[N_EDGES + e]], 1);
}

// ---------------------------------------------------------------------------
// Single-block exclusive prefix scan over g_cnt -> g_off/g_cursor, plus dinv.
// 1024 threads, each owns a contiguous chunk of ceil(N/1024) nodes.
// ---------------------------------------------------------------------------
__global__ __launch_bounds__(1024) void k_offsets() {
    const int TPB = 1024;
    const int PER = (N_NODES + TPB - 1) / TPB;   // 49
    __shared__ int warp_sums[32];

    int t = threadIdx.x;
    int lane = t & 31, wid = t >> 5;
    int base = t * PER;

    // pass 1: chunk total
    int total = 0;
    for (int i = 0; i < PER; i++) {
        int n = base + i;
        if (n < N_NODES) total += g_cnt[n];
    }

    // block exclusive scan of totals
    int v = total;
#pragma unroll
    for (int off = 1; off < 32; off <<= 1) {
        int u = __shfl_up_sync(0xffffffff, v, off);
        if (lane >= off) v += u;
    }
    if (lane == 31) warp_sums[wid] = v;
    __syncthreads();
    if (wid == 0) {
        int w = warp_sums[lane];
#pragma unroll
        for (int off = 1; off < 32; off <<= 1) {
            int u = __shfl_up_sync(0xffffffff, w, off);
            if (lane >= off) w += u;
        }
        warp_sums[lane] = w;
    }
    __syncthreads();
    int excl = v - total + (wid > 0 ? warp_sums[wid - 1] : 0);

    // pass 2: write offsets, cursors, dinv
    int run = excl;
    for (int i = 0; i < PER; i++) {
        int n = base + i;
        if (n < N_NODES) {
            g_off[n] = run;
            g_cursor[n] = run;
            int c = g_cnt[n];
            run += c;
            g_dinv[n] = rsqrtf((float)(c + 1));   // +1 self loop
        }
    }
    if (t == TPB - 1) g_off[N_NODES] = run;
}

__global__ void k_csr(const int* __restrict__ ei) {
    int e = blockIdx.x * blockDim.x + threadIdx.x;
    if (e < N_EDGES) {
        int src = ei[e];
        int dst = ei[N_EDGES + e];
        int pos = atomicAdd(&g_cursor[dst], 1);
        g_srcs[pos] = src;
    }
}

// ---------------------------------------------------------------------------
// SGEMM: h = x @ W.  BM=128, BN=128, BK=32, 256 threads, 8x8 microtile.
// ---------------------------------------------------------------------------
__global__ __launch_bounds__(256) void k_gemm(const float* __restrict__ x,
                                              const float* __restrict__ W) {
    __shared__ float As[32][128];   // [k][m]
    __shared__ float Bs[32][128];   // [k][n]

    const int tid = threadIdx.x;
    const int block_row = blockIdx.x * 128;
    const int tx = tid % 16;
    const int ty = tid / 16;

    float acc[8][8];
#pragma unroll
    for (int i = 0; i < 8; i++)
#pragma unroll
        for (int j = 0; j < 8; j++) acc[i][j] = 0.0f;

    const int aRow = tid / 8;
    const int aCol = (tid % 8) * 4;
    const int bRow = tid / 32;
    const int bCol = (tid % 32) * 4;

    for (int k0 = 0; k0 < IN_DIM; k0 += 32) {
#pragma unroll
        for (int p = 0; p < 4; p++) {
            int m = aRow + p * 32;
            int gm = block_row + m;
            float4 v = make_float4(0.f, 0.f, 0.f, 0.f);
            if (gm < N_NODES)
                v = *(const float4*)&x[(size_t)gm * IN_DIM + k0 + aCol];
            As[aCol + 0][m] = v.x;
            As[aCol + 1][m] = v.y;
            As[aCol + 2][m] = v.z;
            As[aCol + 3][m] = v.w;
        }
#pragma unroll
        for (int p = 0; p < 4; p++) {
            int k = bRow + p * 8;
            *(float4*)&Bs[k][bCol] = *(const float4*)&W[(size_t)(k0 + k) * OUT_DIM + bCol];
        }
        __syncthreads();

#pragma unroll
        for (int kk = 0; kk < 32; kk++) {
            float ra[8], rb[8];
#pragma unroll
            for (int i = 0; i < 8; i++) ra[i] = As[kk][ty * 8 + i];
#pragma unroll
            for (int j = 0; j < 8; j++) rb[j] = Bs[kk][tx * 8 + j];
#pragma unroll
            for (int i = 0; i < 8; i++)
#pragma unroll
                for (int j = 0; j < 8; j++)
                    acc[i][j] = fmaf(ra[i], rb[j], acc[i][j]);
        }
        __syncthreads();
    }

#pragma unroll
    for (int i = 0; i < 8; i++) {
        int gm = block_row + ty * 8 + i;
        if (gm >= N_NODES) break;
#pragma unroll
        for (int j = 0; j < 8; j += 4) {
            g_h4[gm * (OUT_DIM / 4) + (tx * 8 + j) / 4] =
                make_float4(acc[i][j], acc[i][j + 1], acc[i][j + 2], acc[i][j + 3]);
        }
    }
}

// ---------------------------------------------------------------------------
// Fused CSR gather + spiking scan.
// One warp per dst node; lane = one float4 of the 128-dim feature.
//   agg = h[dst]*dinv[dst]^2 + sum_e h[src_e]*dinv[src_e]*dinv[dst]
//   u = 0.1*agg; T=8 LIF steps; out = o_seq[8,N,128] then z_seq[8,N,128]
// ---------------------------------------------------------------------------
__global__ __launch_bounds__(256) void k_gather_scan(float4* __restrict__ out) {
    int node = (blockIdx.x * 256 + threadIdx.x) >> 5;
    int lane = threadIdx.x & 31;
    if (node >= N_NODES) return;

    float di = g_dinv[node];
    float4 hv = g_h4[node * 32 + lane];
    float di2 = di * di;
    float4 acc = make_float4(hv.x * di2, hv.y * di2, hv.z * di2, hv.w * di2);

    int e = g_off[node];
    int end = g_off[node + 1];

    // 4x unrolled main loop for MLP
    for (; e + 4 <= end; e += 4) {
        int s0 = g_srcs[e + 0], s1 = g_srcs[e + 1];
        int s2 = g_srcs[e + 2], s3 = g_srcs[e + 3];
        float n0 = g_dinv[s0] * di, n1 = g_dinv[s1] * di;
        float n2 = g_dinv[s2] * di, n3 = g_dinv[s3] * di;
        float4 v0 = g_h4[s0 * 32 + lane];
        float4 v1 = g_h4[s1 * 32 + lane];
        float4 v2 = g_h4[s2 * 32 + lane];
        float4 v3 = g_h4[s3 * 32 + lane];
        acc.x += v0.x * n0 + v1.x * n1 + v2.x * n2 + v3.x * n3;
        acc.y += v0.y * n0 + v1.y * n1 + v2.y * n2 + v3.y * n3;
        acc.z += v0.z * n0 + v1.z * n1 + v2.z * n2 + v3.z * n3;
        acc.w += v0.w * n0 + v1.w * n1 + v2.w * n2 + v3.w * n3;
    }
    for (; e < end; e++) {
        int s = g_srcs[e];
        float nr = g_dinv[s] * di;
        float4 v = g_h4[s * 32 + lane];
        acc.x += v.x * nr; acc.y += v.y * nr;
        acc.z += v.z * nr; acc.w += v.w * nr;
    }

    // spiking scan, straight from registers
    const int VEC = N_NODES * OUT_DIM / 4;
    int i = node * 32 + lane;
    float4 u = make_float4(acc.x * 0.1f, acc.y * 0.1f, acc.z * 0.1f, acc.w * 0.1f);
    float4 z = make_float4(0.f, 0.f, 0.f, 0.f);

#pragma unroll
    for (int t = 0; t < T_STEPS; t++) {
        float4 Hm = make_float4(z.x + (u.x - z.x) * 0.5f,
                                z.y + (u.y - z.y) * 0.5f,
                                z.z + (u.z - z.z) * 0.5f,
                                z.w + (u.w - z.w) * 0.5f);
        float4 o = make_float4(Hm.x >= 1.0f ? 1.f : 0.f,
                               Hm.y >= 1.0f ? 1.f : 0.f,
                               Hm.z >= 1.0f ? 1.f : 0.f,
                               Hm.w >= 1.0f ? 1.f : 0.f);
        z = make_float4(Hm.x - o.x, Hm.y - o.y, Hm.z - o.z, Hm.w - o.w);
        out[(size_t)t * VEC + i] = o;
        out[(size_t)(T_STEPS + t) * VEC + i] = z;
    }
}

// ---------------------------------------------------------------------------
extern "C" void kernel_launch(void* const* d_in, const int* in_sizes, int n_in,
                              void* d_out, int out_size) {
    const float* x = (const float*)d_in[0];
    const float* W = (const float*)d_in[1];
    const int* ei = (const int*)d_in[2];
    float4* out = (float4*)d_out;

    k_zero_cnt<<<(N_NODES + 255) / 256, 256>>>();
    k_hist<<<(N_EDGES + 255) / 256, 256>>>(ei);
    k_offsets<<<1, 1024>>>();
    k_csr<<<(N_EDGES + 255) / 256, 256>>>(ei);
    k_gemm<<<(N_NODES + 127) / 128, 256>>>(x, W);
    k_gather_scan<<<(N_NODES * 32 + 255) / 256, 256>>>(out);
}

// round 5
// speedup vs baseline: 1.2007x; 1.0948x over previous
#include <cuda_runtime.h>
#include <cstdint>

#define N_NODES 50000
#define N_EDGES 1600000
#define IN_DIM  256
#define OUT_DIM 128
#define T_STEPS 8

// Scratch (device globals — no allocation allowed)
__device__ __align__(16) float4 g_h4[N_NODES * OUT_DIM / 4];  // h = x @ W
__device__ float g_dinv[N_NODES];
__device__ int   g_cnt[N_NODES];        // in-edge count (no self loop)
__device__ int   g_off[N_NODES + 1];    // CSR offsets by dst
__device__ int   g_cursor[N_NODES];     // scatter cursors
__device__ int   g_srcs[N_EDGES];       // CSR column (src) indices

// ---------------------------------------------------------------------------
__global__ void k_zero_cnt() {
    int n = blockIdx.x * blockDim.x + threadIdx.x;
    if (n < N_NODES) g_cnt[n] = 0;
}

__global__ void k_hist(const int* __restrict__ ei) {
    int e = blockIdx.x * blockDim.x + threadIdx.x;
    if (e < N_EDGES) atomicAdd(&g_cnt[ei[N_EDGES + e]], 1);
}

// ---------------------------------------------------------------------------
// Single-block exclusive prefix scan over g_cnt -> g_off/g_cursor, plus dinv.
// ---------------------------------------------------------------------------
__global__ __launch_bounds__(1024) void k_offsets() {
    const int TPB = 1024;
    const int PER = (N_NODES + TPB - 1) / TPB;   // 49
    __shared__ int warp_sums[32];

    int t = threadIdx.x;
    int lane = t & 31, wid = t >> 5;
    int base = t * PER;

    int total = 0;
    for (int i = 0; i < PER; i++) {
        int n = base + i;
        if (n < N_NODES) total += g_cnt[n];
    }

    int v = total;
#pragma unroll
    for (int off = 1; off < 32; off <<= 1) {
        int u = __shfl_up_sync(0xffffffff, v, off);
        if (lane >= off) v += u;
    }
    if (lane == 31) warp_sums[wid] = v;
    __syncthreads();
    if (wid == 0) {
        int w = warp_sums[lane];
#pragma unroll
        for (int off = 1; off < 32; off <<= 1) {
            int u = __shfl_up_sync(0xffffffff, w, off);
            if (lane >= off) w += u;
        }
        warp_sums[lane] = w;
    }
    __syncthreads();
    int excl = v - total + (wid > 0 ? warp_sums[wid - 1] : 0);

    int run = excl;
    for (int i = 0; i < PER; i++) {
        int n = base + i;
        if (n < N_NODES) {
            g_off[n] = run;
            g_cursor[n] = run;
            int c = g_cnt[n];
            run += c;
            g_dinv[n] = rsqrtf((float)(c + 1));   // +1 self loop
        }
    }
    if (t == TPB - 1) g_off[N_NODES] = run;
}

__global__ void k_csr(const int* __restrict__ ei) {
    int e = blockIdx.x * blockDim.x + threadIdx.x;
    if (e < N_EDGES) {
        int src = ei[e];
        int dst = ei[N_EDGES + e];
        int pos = atomicAdd(&g_cursor[dst], 1);
        g_srcs[pos] = src;
    }
}

// ---------------------------------------------------------------------------
// SGEMM: h = x @ W.  BM=128, BN=128, BK=32, 256 threads, 8x8 microtile.
// ---------------------------------------------------------------------------
__global__ __launch_bounds__(256) void k_gemm(const float* __restrict__ x,
                                              const float* __restrict__ W) {
    __shared__ float As[32][128];   // [k][m]
    __shared__ float Bs[32][128];   // [k][n]

    const int tid = threadIdx.x;
    const int block_row = blockIdx.x * 128;
    const int tx = tid % 16;
    const int ty = tid / 16;

    float acc[8][8];
#pragma unroll
    for (int i = 0; i < 8; i++)
#pragma unroll
        for (int j = 0; j < 8; j++) acc[i][j] = 0.0f;

    const int aRow = tid / 8;
    const int aCol = (tid % 8) * 4;
    const int bRow = tid / 32;
    const int bCol = (tid % 32) * 4;

    for (int k0 = 0; k0 < IN_DIM; k0 += 32) {
#pragma unroll
        for (int p = 0; p < 4; p++) {
            int m = aRow + p * 32;
            int gm = block_row + m;
            float4 v = make_float4(0.f, 0.f, 0.f, 0.f);
            if (gm < N_NODES)
                v = *(const float4*)&x[(size_t)gm * IN_DIM + k0 + aCol];
            As[aCol + 0][m] = v.x;
            As[aCol + 1][m] = v.y;
            As[aCol + 2][m] = v.z;
            As[aCol + 3][m] = v.w;
        }
#pragma unroll
        for (int p = 0; p < 4; p++) {
            int k = bRow + p * 8;
            *(float4*)&Bs[k][bCol] = *(const float4*)&W[(size_t)(k0 + k) * OUT_DIM + bCol];
        }
        __syncthreads();

#pragma unroll
        for (int kk = 0; kk < 32; kk++) {
            float ra[8], rb[8];
#pragma unroll
            for (int i = 0; i < 8; i++) ra[i] = As[kk][ty * 8 + i];
#pragma unroll
            for (int j = 0; j < 8; j++) rb[j] = Bs[kk][tx * 8 + j];
#pragma unroll
            for (int i = 0; i < 8; i++)
#pragma unroll
                for (int j = 0; j < 8; j++)
                    acc[i][j] = fmaf(ra[i], rb[j], acc[i][j]);
        }
        __syncthreads();
    }

#pragma unroll
    for (int i = 0; i < 8; i++) {
        int gm = block_row + ty * 8 + i;
        if (gm >= N_NODES) break;
#pragma unroll
        for (int j = 0; j < 8; j += 4) {
            g_h4[gm * (OUT_DIM / 4) + (tx * 8 + j) / 4] =
                make_float4(acc[i][j], acc[i][j + 1], acc[i][j + 2], acc[i][j + 3]);
        }
    }
}

// ---------------------------------------------------------------------------
// Fused CSR gather + spiking scan.
// One warp per dst node; lane = one float4 of the 128-dim feature.
// Output stores use st.global.cs (evict-first) to keep g_h4 L2-resident.
// ---------------------------------------------------------------------------
__global__ __launch_bounds__(256) void k_gather_scan(float4* __restrict__ out) {
    int node = (blockIdx.x * 256 + threadIdx.x) >> 5;
    int lane = threadIdx.x & 31;
    if (node >= N_NODES) return;

    float di = g_dinv[node];
    float4 hv = g_h4[node * 32 + lane];
    float di2 = di * di;
    float4 acc = make_float4(hv.x * di2, hv.y * di2, hv.z * di2, hv.w * di2);

    int e = g_off[node];
    int end = g_off[node + 1];

    for (; e + 4 <= end; e += 4) {
        int s0 = g_srcs[e + 0], s1 = g_srcs[e + 1];
        int s2 = g_srcs[e + 2], s3 = g_srcs[e + 3];
        float n0 = g_dinv[s0] * di, n1 = g_dinv[s1] * di;
        float n2 = g_dinv[s2] * di, n3 = g_dinv[s3] * di;
        float4 v0 = g_h4[s0 * 32 + lane];
        float4 v1 = g_h4[s1 * 32 + lane];
        float4 v2 = g_h4[s2 * 32 + lane];
        float4 v3 = g_h4[s3 * 32 + lane];
        acc.x += v0.x * n0 + v1.x * n1 + v2.x * n2 + v3.x * n3;
        acc.y += v0.y * n0 + v1.y * n1 + v2.y * n2 + v3.y * n3;
        acc.z += v0.z * n0 + v1.z * n1 + v2.z * n2 + v3.z * n3;
        acc.w += v0.w * n0 + v1.w * n1 + v2.w * n2 + v3.w * n3;
    }
    for (; e < end; e++) {
        int s = g_srcs[e];
        float nr = g_dinv[s] * di;
        float4 v = g_h4[s * 32 + lane];
        acc.x += v.x * nr; acc.y += v.y * nr;
        acc.z += v.z * nr; acc.w += v.w * nr;
    }

    const int VEC = N_NODES * OUT_DIM / 4;
    int i = node * 32 + lane;
    float4 u = make_float4(acc.x * 0.1f, acc.y * 0.1f, acc.z * 0.1f, acc.w * 0.1f);
    float4 z = make_float4(0.f, 0.f, 0.f, 0.f);

#pragma unroll
    for (int t = 0; t < T_STEPS; t++) {
        float4 Hm = make_float4(z.x + (u.x - z.x) * 0.5f,
                                z.y + (u.y - z.y) * 0.5f,
                                z.z + (u.z - z.z) * 0.5f,
                                z.w + (u.w - z.w) * 0.5f);
        float4 o = make_float4(Hm.x >= 1.0f ? 1.f : 0.f,
                               Hm.y >= 1.0f ? 1.f : 0.f,
                               Hm.z >= 1.0f ? 1.f : 0.f,
                               Hm.w >= 1.0f ? 1.f : 0.f);
        z = make_float4(Hm.x - o.x, Hm.y - o.y, Hm.z - o.z, Hm.w - o.w);
        __stcs(&out[(size_t)t * VEC + i], o);
        __stcs(&out[(size_t)(T_STEPS + t) * VEC + i], z);
    }
}

// ---------------------------------------------------------------------------
// Fork-join: CSR chain on a side stream, GEMM on the main (capture) stream.
// Stream/events created once on the first (uncaptured correctness) call;
// event record/wait are graph-capturable and encode the dependency edges.
// ---------------------------------------------------------------------------
static cudaStream_t s_side = nullptr;
static cudaEvent_t  s_ev_fork = nullptr, s_ev_join = nullptr;

extern "C" void kernel_launch(void* const* d_in, const int* in_sizes, int n_in,
                              void* d_out, int out_size) {
    const float* x = (const float*)d_in[0];
    const float* W = (const float*)d_in[1];
    const int* ei = (const int*)d_in[2];
    float4* out = (float4*)d_out;

    if (s_side == nullptr) {
        cudaStreamCreateWithFlags(&s_side, cudaStreamNonBlocking);
        cudaEventCreateWithFlags(&s_ev_fork, cudaEventDisableTiming);
        cudaEventCreateWithFlags(&s_ev_join, cudaEventDisableTiming);
    }

    // fork
    cudaEventRecord(s_ev_fork, 0);
    cudaStreamWaitEvent(s_side, s_ev_fork, 0);

    // side stream: CSR build chain
    k_zero_cnt<<<(N_NODES + 255) / 256, 256, 0, s_side>>>();
    k_hist<<<(N_EDGES + 255) / 256, 256, 0, s_side>>>(ei);
    k_offsets<<<1, 1024, 0, s_side>>>();
    k_csr<<<(N_EDGES + 255) / 256, 256, 0, s_side>>>(ei);
    cudaEventRecord(s_ev_join, s_side);

    // main stream: GEMM (independent of CSR)
    k_gemm<<<(N_NODES + 127) / 128, 256>>>(x, W);

    // join, then fused gather+scan
    cudaStreamWaitEvent(0, s_ev_join, 0);
    k_gather_scan<<<(N_NODES * 32 + 255) / 256, 256>>>(out);
}

// round 6
// speedup vs baseline: 1.2008x; 1.0001x over previous
#include <cuda_runtime.h>
#include <cstdint>

#define N_NODES 50000
#define N_EDGES 1600000
#define IN_DIM  256
#define OUT_DIM 128
#define T_STEPS 8

// Scratch (device globals — no allocation allowed)
__device__ __align__(16) float4 g_h4[N_NODES * OUT_DIM / 4];  // h = x @ W
__device__ float g_dinv[N_NODES];
__device__ int   g_cnt[N_NODES];        // in-edge count (no self loop)
__device__ int   g_off[N_NODES + 1];    // CSR offsets by dst
__device__ int   g_cursor[N_NODES];     // scatter cursors
__device__ int   g_srcs[N_EDGES];       // CSR column (src) indices

// ---------------------------------------------------------------------------
__global__ void k_zero_cnt() {
    int n = blockIdx.x * blockDim.x + threadIdx.x;
    if (n < N_NODES) g_cnt[n] = 0;
}

__global__ void k_hist(const int* __restrict__ ei) {
    int e = blockIdx.x * blockDim.x + threadIdx.x;
    if (e < N_EDGES) atomicAdd(&g_cnt[ei[N_EDGES + e]], 1);
}

// ---------------------------------------------------------------------------
// Single-block exclusive prefix scan over g_cnt -> g_off/g_cursor, plus dinv.
// ---------------------------------------------------------------------------
__global__ __launch_bounds__(1024) void k_offsets() {
    const int TPB = 1024;
    const int PER = (N_NODES + TPB - 1) / TPB;   // 49
    __shared__ int warp_sums[32];

    int t = threadIdx.x;
    int lane = t & 31, wid = t >> 5;
    int base = t * PER;

    int total = 0;
    for (int i = 0; i < PER; i++) {
        int n = base + i;
        if (n < N_NODES) total += g_cnt[n];
    }

    int v = total;
#pragma unroll
    for (int off = 1; off < 32; off <<= 1) {
        int u = __shfl_up_sync(0xffffffff, v, off);
        if (lane >= off) v += u;
    }
    if (lane == 31) warp_sums[wid] = v;
    __syncthreads();
    if (wid == 0) {
        int w = warp_sums[lane];
#pragma unroll
        for (int off = 1; off < 32; off <<= 1) {
            int u = __shfl_up_sync(0xffffffff, w, off);
            if (lane >= off) w += u;
        }
        warp_sums[lane] = w;
    }
    __syncthreads();
    int excl = v - total + (wid > 0 ? warp_sums[wid - 1] : 0);

    int run = excl;
    for (int i = 0; i < PER; i++) {
        int n = base + i;
        if (n < N_NODES) {
            g_off[n] = run;
            g_cursor[n] = run;
            int c = g_cnt[n];
            run += c;
            g_dinv[n] = rsqrtf((float)(c + 1));   // +1 self loop
        }
    }
    if (t == TPB - 1) g_off[N_NODES] = run;
}

__global__ void k_csr(const int* __restrict__ ei) {
    int e = blockIdx.x * blockDim.x + threadIdx.x;
    if (e < N_EDGES) {
        int src = ei[e];
        int dst = ei[N_EDGES + e];
        int pos = atomicAdd(&g_cursor[dst], 1);
        g_srcs[pos] = src;
    }
}

// ---------------------------------------------------------------------------
// SGEMM: h = x @ W.  BM=128, BN=128, BK=32, 256 threads, 8x8 microtile.
// ---------------------------------------------------------------------------
__global__ __launch_bounds__(256) void k_gemm(const float* __restrict__ x,
                                              const float* __restrict__ W) {
    __shared__ float As[32][128];   // [k][m]
    __shared__ float Bs[32][128];   // [k][n]

    const int tid = threadIdx.x;
    const int block_row = blockIdx.x * 128;
    const int tx = tid % 16;
    const int ty = tid / 16;

    float acc[8][8];
#pragma unroll
    for (int i = 0; i < 8; i++)
#pragma unroll
        for (int j = 0; j < 8; j++) acc[i][j] = 0.0f;

    const int aRow = tid / 8;
    const int aCol = (tid % 8) * 4;
    const int bRow = tid / 32;
    const int bCol = (tid % 32) * 4;

    for (int k0 = 0; k0 < IN_DIM; k0 += 32) {
#pragma unroll
        for (int p = 0; p < 4; p++) {
            int m = aRow + p * 32;
            int gm = block_row + m;
            float4 v = make_float4(0.f, 0.f, 0.f, 0.f);
            if (gm < N_NODES)
                v = *(const float4*)&x[(size_t)gm * IN_DIM + k0 + aCol];
            As[aCol + 0][m] = v.x;
            As[aCol + 1][m] = v.y;
            As[aCol + 2][m] = v.z;
            As[aCol + 3][m] = v.w;
        }
#pragma unroll
        for (int p = 0; p < 4; p++) {
            int k = bRow + p * 8;
            *(float4*)&Bs[k][bCol] = *(const float4*)&W[(size_t)(k0 + k) * OUT_DIM + bCol];
        }
        __syncthreads();

#pragma unroll
        for (int kk = 0; kk < 32; kk++) {
            float ra[8], rb[8];
#pragma unroll
            for (int i = 0; i < 8; i++) ra[i] = As[kk][ty * 8 + i];
#pragma unroll
            for (int j = 0; j < 8; j++) rb[j] = Bs[kk][tx * 8 + j];
#pragma unroll
            for (int i = 0; i < 8; i++)
#pragma unroll
                for (int j = 0; j < 8; j++)
                    acc[i][j] = fmaf(ra[i], rb[j], acc[i][j]);
        }
        __syncthreads();
    }

#pragma unroll
    for (int i = 0; i < 8; i++) {
        int gm = block_row + ty * 8 + i;
        if (gm >= N_NODES) break;
#pragma unroll
        for (int j = 0; j < 8; j += 4) {
            g_h4[gm * (OUT_DIM / 4) + (tx * 8 + j) / 4] =
                make_float4(acc[i][j], acc[i][j + 1], acc[i][j + 2], acc[i][j + 3]);
        }
    }
}

// ---------------------------------------------------------------------------
// Fused CSR gather + spiking scan.
// One warp per dst node. 32-edge windows: each lane coalesced-loads one edge
// index + its dinv (1 LDG vs 32 broadcast LDGs), then the inner loop is
// independent h-gathers broadcast via shfl. Output stores are evict-first.
// ---------------------------------------------------------------------------
__global__ __launch_bounds__(256) void k_gather_scan(float4* __restrict__ out) {
    int node = (blockIdx.x * 256 + threadIdx.x) >> 5;
    int lane = threadIdx.x & 31;
    if (node >= N_NODES) return;

    float di = g_dinv[node];
    float4 hv = g_h4[node * 32 + lane];
    float di2 = di * di;
    float4 acc = make_float4(hv.x * di2, hv.y * di2, hv.z * di2, hv.w * di2);

    int beg = g_off[node];
    int end = g_off[node + 1];

    for (int base = beg; base < end; base += 32) {
        int cnt = end - base;
        if (cnt > 32) cnt = 32;

        // lane-parallel prefetch of 32 edge ids + their dinv (coalesced)
        int   myidx = 0;
        float mynrm = 0.0f;
        if (lane < cnt) {
            myidx = g_srcs[base + lane];
            mynrm = g_dinv[myidx] * di;
        }

        int j = 0;
        for (; j + 4 <= cnt; j += 4) {
            int   s0 = __shfl_sync(0xffffffffu, myidx, j + 0);
            int   s1 = __shfl_sync(0xffffffffu, myidx, j + 1);
            int   s2 = __shfl_sync(0xffffffffu, myidx, j + 2);
            int   s3 = __shfl_sync(0xffffffffu, myidx, j + 3);
            float n0 = __shfl_sync(0xffffffffu, mynrm, j + 0);
            float n1 = __shfl_sync(0xffffffffu, mynrm, j + 1);
            float n2 = __shfl_sync(0xffffffffu, mynrm, j + 2);
            float n3 = __shfl_sync(0xffffffffu, mynrm, j + 3);
            float4 v0 = g_h4[s0 * 32 + lane];
            float4 v1 = g_h4[s1 * 32 + lane];
            float4 v2 = g_h4[s2 * 32 + lane];
            float4 v3 = g_h4[s3 * 32 + lane];
            acc.x += v0.x * n0 + v1.x * n1 + v2.x * n2 + v3.x * n3;
            acc.y += v0.y * n0 + v1.y * n1 + v2.y * n2 + v3.y * n3;
            acc.z += v0.z * n0 + v1.z * n1 + v2.z * n2 + v3.z * n3;
            acc.w += v0.w * n0 + v1.w * n1 + v2.w * n2 + v3.w * n3;
        }
        for (; j < cnt; j++) {
            int   s = __shfl_sync(0xffffffffu, myidx, j);
            float nr = __shfl_sync(0xffffffffu, mynrm, j);
            float4 v = g_h4[s * 32 + lane];
            acc.x += v.x * nr; acc.y += v.y * nr;
            acc.z += v.z * nr; acc.w += v.w * nr;
        }
    }

    // spiking scan, straight from registers
    const int VEC = N_NODES * OUT_DIM / 4;
    int i = node * 32 + lane;
    float4 u = make_float4(acc.x * 0.1f, acc.y * 0.1f, acc.z * 0.1f, acc.w * 0.1f);
    float4 z = make_float4(0.f, 0.f, 0.f, 0.f);

#pragma unroll
    for (int t = 0; t < T_STEPS; t++) {
        float4 Hm = make_float4(z.x + (u.x - z.x) * 0.5f,
                                z.y + (u.y - z.y) * 0.5f,
                                z.z + (u.z - z.z) * 0.5f,
                                z.w + (u.w - z.w) * 0.5f);
        float4 o = make_float4(Hm.x >= 1.0f ? 1.f : 0.f,
                               Hm.y >= 1.0f ? 1.f : 0.f,
                               Hm.z >= 1.0f ? 1.f : 0.f,
                               Hm.w >= 1.0f ? 1.f : 0.f);
        z = make_float4(Hm.x - o.x, Hm.y - o.y, Hm.z - o.z, Hm.w - o.w);
        __stcs(&out[(size_t)t * VEC + i], o);
        __stcs(&out[(size_t)(T_STEPS + t) * VEC + i], z);
    }
}

// ---------------------------------------------------------------------------
// Fork-join: CSR chain on a side stream, GEMM on the main (capture) stream.
// ---------------------------------------------------------------------------
static cudaStream_t s_side = nullptr;
static cudaEvent_t  s_ev_fork = nullptr, s_ev_join = nullptr;

extern "C" void kernel_launch(void* const* d_in, const int* in_sizes, int n_in,
                              void* d_out, int out_size) {
    const float* x = (const float*)d_in[0];
    const float* W = (const float*)d_in[1];
    const int* ei = (const int*)d_in[2];
    float4* out = (float4*)d_out;

    if (s_side == nullptr) {
        cudaStreamCreateWithFlags(&s_side, cudaStreamNonBlocking);
        cudaEventCreateWithFlags(&s_ev_fork, cudaEventDisableTiming);
        cudaEventCreateWithFlags(&s_ev_join, cudaEventDisableTiming);
    }

    // fork
    cudaEventRecord(s_ev_fork, 0);
    cudaStreamWaitEvent(s_side, s_ev_fork, 0);

    // side stream: CSR build chain
    k_zero_cnt<<<(N_NODES + 255) / 256, 256, 0, s_side>>>();
    k_hist<<<(N_EDGES + 255) / 256, 256, 0, s_side>>>(ei);
    k_offsets<<<1, 1024, 0, s_side>>>();
    k_csr<<<(N_EDGES + 255) / 256, 256, 0, s_side>>>(ei);
    cudaEventRecord(s_ev_join, s_side);

    // main stream: GEMM (independent of CSR)
    k_gemm<<<(N_NODES + 127) / 128, 256>>>(x, W);

    // join, then fused gather+scan
    cudaStreamWaitEvent(0, s_ev_join, 0);
    k_gather_scan<<<(N_NODES * 32 + 255) / 256, 256>>>(out);
}

// round 7
// speedup vs baseline: 1.2490x; 1.0402x over previous
#include <cuda_runtime.h>
#include <cuda_fp16.h>
#include <cstdint>

#define N_NODES 50000
#define N_EDGES 1600000
#define IN_DIM  256
#define OUT_DIM 128
#define T_STEPS 8

// Scratch (device globals — no allocation allowed)
__device__ __align__(16) __half g_h2[N_NODES * OUT_DIM];  // h = x @ W (fp16)
__device__ float g_dinv[N_NODES];
__device__ int   g_cnt[N_NODES];
__device__ int   g_off[N_NODES + 1];
__device__ int   g_cursor[N_NODES];
__device__ int   g_srcs[N_EDGES];

// ---------------------------------------------------------------------------
__global__ void k_zero_cnt() {
    int n = blockIdx.x * blockDim.x + threadIdx.x;
    if (n < N_NODES) g_cnt[n] = 0;
}

__global__ void k_hist(const int* __restrict__ ei) {
    int e = blockIdx.x * blockDim.x + threadIdx.x;
    if (e < N_EDGES) atomicAdd(&g_cnt[ei[N_EDGES + e]], 1);
}

// ---------------------------------------------------------------------------
__global__ __launch_bounds__(1024) void k_offsets() {
    const int TPB = 1024;
    const int PER = (N_NODES + TPB - 1) / TPB;
    __shared__ int warp_sums[32];

    int t = threadIdx.x;
    int lane = t & 31, wid = t >> 5;
    int base = t * PER;

    int total = 0;
    for (int i = 0; i < PER; i++) {
        int n = base + i;
        if (n < N_NODES) total += g_cnt[n];
    }

    int v = total;
#pragma unroll
    for (int off = 1; off < 32; off <<= 1) {
        int u = __shfl_up_sync(0xffffffff, v, off);
        if (lane >= off) v += u;
    }
    if (lane == 31) warp_sums[wid] = v;
    __syncthreads();
    if (wid == 0) {
        int w = warp_sums[lane];
#pragma unroll
        for (int off = 1; off < 32; off <<= 1) {
            int u = __shfl_up_sync(0xffffffff, w, off);
            if (lane >= off) w += u;
        }
        warp_sums[lane] = w;
    }
    __syncthreads();
    int excl = v - total + (wid > 0 ? warp_sums[wid - 1] : 0);

    int run = excl;
    for (int i = 0; i < PER; i++) {
        int n = base + i;
        if (n < N_NODES) {
            g_off[n] = run;
            g_cursor[n] = run;
            int c = g_cnt[n];
            run += c;
            g_dinv[n] = rsqrtf((float)(c + 1));
        }
    }
    if (t == TPB - 1) g_off[N_NODES] = run;
}

__global__ void k_csr(const int* __restrict__ ei) {
    int e = blockIdx.x * blockDim.x + threadIdx.x;
    if (e < N_EDGES) {
        int src = ei[e];
        int dst = ei[N_EDGES + e];
        int pos = atomicAdd(&g_cursor[dst], 1);
        g_srcs[pos] = src;
    }
}

// ---------------------------------------------------------------------------
// SGEMM: h = x @ W, store fp16.  BM=128, BN=128, BK=32, 256 thr, 8x8 tile.
// ---------------------------------------------------------------------------
__global__ __launch_bounds__(256) void k_gemm(const float* __restrict__ x,
                                              const float* __restrict__ W) {
    __shared__ float As[32][128];
    __shared__ float Bs[32][128];

    const int tid = threadIdx.x;
    const int block_row = blockIdx.x * 128;
    const int tx = tid % 16;
    const int ty = tid / 16;

    float acc[8][8];
#pragma unroll
    for (int i = 0; i < 8; i++)
#pragma unroll
        for (int j = 0; j < 8; j++) acc[i][j] = 0.0f;

    const int aRow = tid / 8;
    const int aCol = (tid % 8) * 4;
    const int bRow = tid / 32;
    const int bCol = (tid % 32) * 4;

    for (int k0 = 0; k0 < IN_DIM; k0 += 32) {
#pragma unroll
        for (int p = 0; p < 4; p++) {
            int m = aRow + p * 32;
            int gm = block_row + m;
            float4 v = make_float4(0.f, 0.f, 0.f, 0.f);
            if (gm < N_NODES)
                v = *(const float4*)&x[(size_t)gm * IN_DIM + k0 + aCol];
            As[aCol + 0][m] = v.x;
            As[aCol + 1][m] = v.y;
            As[aCol + 2][m] = v.z;
            As[aCol + 3][m] = v.w;
        }
#pragma unroll
        for (int p = 0; p < 4; p++) {
            int k = bRow + p * 8;
            *(float4*)&Bs[k][bCol] = *(const float4*)&W[(size_t)(k0 + k) * OUT_DIM + bCol];
        }
        __syncthreads();

#pragma unroll
        for (int kk = 0; kk < 32; kk++) {
            float ra[8], rb[8];
#pragma unroll
            for (int i = 0; i < 8; i++) ra[i] = As[kk][ty * 8 + i];
#pragma unroll
            for (int j = 0; j < 8; j++) rb[j] = Bs[kk][tx * 8 + j];
#pragma unroll
            for (int i = 0; i < 8; i++)
#pragma unroll
                for (int j = 0; j < 8; j++)
                    acc[i][j] = fmaf(ra[i], rb[j], acc[i][j]);
        }
        __syncthreads();
    }

#pragma unroll
    for (int i = 0; i < 8; i++) {
        int gm = block_row + ty * 8 + i;
        if (gm >= N_NODES) break;
        // pack 8 floats -> 8 halves -> one 16B store (cols tx*8 .. tx*8+7)
        __half2 p0 = __floats2half2_rn(acc[i][0], acc[i][1]);
        __half2 p1 = __floats2half2_rn(acc[i][2], acc[i][3]);
        __half2 p2 = __floats2half2_rn(acc[i][4], acc[i][5]);
        __half2 p3 = __floats2half2_rn(acc[i][6], acc[i][7]);
        uint4 pk;
        pk.x = *(uint32_t*)&p0; pk.y = *(uint32_t*)&p1;
        pk.z = *(uint32_t*)&p2; pk.w = *(uint32_t*)&p3;
        *(uint4*)&g_h2[(size_t)gm * OUT_DIM + tx * 8] = pk;
    }
}

// ---------------------------------------------------------------------------
// Fused CSR gather (fp16 h) + spiking scan.
// One warp per dst node; HALF-warp per edge: 16 lanes x 16B = 256B row.
// Lane owns 8 dims (base=(lane&15)*8); halves accumulate even/odd edges,
// reduced at the end via shfl_xor(16). Self-loop added in half 0 only.
// ---------------------------------------------------------------------------
__global__ __launch_bounds__(256) void k_gather_scan(float4* __restrict__ out) {
    int node = (blockIdx.x * 256 + threadIdx.x) >> 5;
    int lane = threadIdx.x & 31;
    if (node >= N_NODES) return;

    const int l16 = lane & 15;
    const int sel = lane >> 4;     // which half-warp

    float di = g_dinv[node];
    float acc[8];
#pragma unroll
    for (int k = 0; k < 8; k++) acc[k] = 0.0f;

    // self-loop: h[node]*di^2, counted once (half 0 only)
    if (sel == 0) {
        uint4 v = *(const uint4*)&g_h2[(size_t)node * OUT_DIM + l16 * 8];
        const __half2* hp = (const __half2*)&v;
        float di2 = di * di;
#pragma unroll
        for (int q = 0; q < 4; q++) {
            float2 f = __half22float2(hp[q]);
            acc[2 * q + 0] = f.x * di2;
            acc[2 * q + 1] = f.y * di2;
        }
    }

    int beg = g_off[node];
    int end = g_off[node + 1];

    for (int base = beg; base < end; base += 32) {
        int cnt = end - base;
        if (cnt > 32) cnt = 32;

        // lane-parallel prefetch of up to 32 edge ids + norms (coalesced)
        int   myidx = 0;
        float mynrm = 0.0f;
        if (lane < cnt) {
            myidx = g_srcs[base + lane];
            mynrm = g_dinv[myidx] * di;
        }

        int j = 0;
        // 8 edges per iter: 4 independent gathers per lane (MLP)
        for (; j + 8 <= cnt; j += 8) {
#pragma unroll
            for (int p = 0; p < 4; p++) {
                int   s  = __shfl_sync(0xffffffffu, myidx, j + 2 * p + sel);
                float nr = __shfl_sync(0xffffffffu, mynrm, j + 2 * p + sel);
                uint4 v = *(const uint4*)&g_h2[(size_t)s * OUT_DIM + l16 * 8];
                const __half2* hp = (const __half2*)&v;
#pragma unroll
                for (int q = 0; q < 4; q++) {
                    float2 f = __half22float2(hp[q]);
                    acc[2 * q + 0] += f.x * nr;
                    acc[2 * q + 1] += f.y * nr;
                }
            }
        }
        // 2 edges per iter
        for (; j + 2 <= cnt; j += 2) {
            int   s  = __shfl_sync(0xffffffffu, myidx, j + sel);
            float nr = __shfl_sync(0xffffffffu, mynrm, j + sel);
            uint4 v = *(const uint4*)&g_h2[(size_t)s * OUT_DIM + l16 * 8];
            const __half2* hp = (const __half2*)&v;
#pragma unroll
            for (int q = 0; q < 4; q++) {
                float2 f = __half22float2(hp[q]);
                acc[2 * q + 0] += f.x * nr;
                acc[2 * q + 1] += f.y * nr;
            }
        }
        // odd tail: half 0 only
        if (j < cnt) {
            int   s  = __shfl_sync(0xffffffffu, myidx, j);
            float nr = __shfl_sync(0xffffffffu, mynrm, j);
            if (sel == 0) {
                uint4 v = *(const uint4*)&g_h2[(size_t)s * OUT_DIM + l16 * 8];
                const __half2* hp = (const __half2*)&v;
#pragma unroll
                for (int q = 0; q < 4; q++) {
                    float2 f = __half22float2(hp[q]);
                    acc[2 * q + 0] += f.x * nr;
                    acc[2 * q + 1] += f.y * nr;
                }
            }
        }
    }

    // cross-half reduction: both halves now hold full sums for their 8 dims
#pragma unroll
    for (int k = 0; k < 8; k++)
        acc[k] += __shfl_xor_sync(0xffffffffu, acc[k], 16);

    // spiking scan on this lane's 4 chosen dims (sel picks which float4)
    const int VEC = N_NODES * OUT_DIM / 4;
    int i = node * 32 + l16 * 2 + sel;
    int b = 4 * sel;
    float4 u = make_float4(acc[b + 0] * 0.1f, acc[b + 1] * 0.1f,
                           acc[b + 2] * 0.1f, acc[b + 3] * 0.1f);
    float4 z = make_float4(0.f, 0.f, 0.f, 0.f);

#pragma unroll
    for (int t = 0; t < T_STEPS; t++) {
        float4 Hm = make_float4(z.x + (u.x - z.x) * 0.5f,
                                z.y + (u.y - z.y) * 0.5f,
                                z.z + (u.z - z.z) * 0.5f,
                                z.w + (u.w - z.w) * 0.5f);
        float4 o = make_float4(Hm.x >= 1.0f ? 1.f : 0.f,
                               Hm.y >= 1.0f ? 1.f : 0.f,
                               Hm.z >= 1.0f ? 1.f : 0.f,
                               Hm.w >= 1.0f ? 1.f : 0.f);
        z = make_float4(Hm.x - o.x, Hm.y - o.y, Hm.z - o.z, Hm.w - o.w);
        __stcs(&out[(size_t)t * VEC + i], o);
        __stcs(&out[(size_t)(T_STEPS + t) * VEC + i], z);
    }
}

// ---------------------------------------------------------------------------
static cudaStream_t s_side = nullptr;
static cudaEvent_t  s_ev_fork = nullptr, s_ev_join = nullptr;

extern "C" void kernel_launch(void* const* d_in, const int* in_sizes, int n_in,
                              void* d_out, int out_size) {
    const float* x = (const float*)d_in[0];
    const float* W = (const float*)d_in[1];
    const int* ei = (const int*)d_in[2];
    float4* out = (float4*)d_out;

    if (s_side == nullptr) {
        cudaStreamCreateWithFlags(&s_side, cudaStreamNonBlocking);
        cudaEventCreateWithFlags(&s_ev_fork, cudaEventDisableTiming);
        cudaEventCreateWithFlags(&s_ev_join, cudaEventDisableTiming);
    }

    cudaEventRecord(s_ev_fork, 0);
    cudaStreamWaitEvent(s_side, s_ev_fork, 0);

    // side stream: CSR build chain
    k_zero_cnt<<<(N_NODES + 255) / 256, 256, 0, s_side>>>();
    k_hist<<<(N_EDGES + 255) / 256, 256, 0, s_side>>>(ei);
    k_offsets<<<1, 1024, 0, s_side>>>();
    k_csr<<<(N_EDGES + 255) / 256, 256, 0, s_side>>>(ei);
    cudaEventRecord(s_ev_join, s_side);

    // main stream: GEMM
    k_gemm<<<(N_NODES + 127) / 128, 256>>>(x, W);

    cudaStreamWaitEvent(0, s_ev_join, 0);
    k_gather_scan<<<(N_NODES * 32 + 255) / 256, 256>>>(out);
}

// round 8
// speedup vs baseline: 1.5445x; 1.2366x over previous
#include <cuda_runtime.h>
#include <cuda_fp16.h>
#include <mma.h>
#include <cstdint>

using namespace nvcuda;

#define N_NODES 50000
#define N_PAD   50048   // 782 * 64
#define N_EDGES 1600000
#define IN_DIM  256
#define OUT_DIM 128
#define T_STEPS 8

// Scratch (device globals — no allocation allowed)
__device__ __align__(16) __half g_x2[N_PAD * IN_DIM];    // x in fp16 (padded)
__device__ __align__(16) __half g_h2[N_PAD * OUT_DIM];   // h = x @ W (fp16)
__device__ float g_dinv[N_NODES];
__device__ int   g_cnt[N_NODES];
__device__ int   g_off[N_NODES + 1];
__device__ int   g_cursor[N_NODES];
__device__ int   g_srcs[N_EDGES];

// ---------------------------------------------------------------------------
__global__ void k_zero_cnt() {
    int n = blockIdx.x * blockDim.x + threadIdx.x;
    if (n < N_NODES) g_cnt[n] = 0;
}

__global__ void k_hist(const int* __restrict__ ei) {
    int e = blockIdx.x * blockDim.x + threadIdx.x;
    if (e < N_EDGES) atomicAdd(&g_cnt[ei[N_EDGES + e]], 1);
}

// ---------------------------------------------------------------------------
__global__ __launch_bounds__(1024) void k_offsets() {
    const int TPB = 1024;
    const int PER = (N_NODES + TPB - 1) / TPB;
    __shared__ int warp_sums[32];

    int t = threadIdx.x;
    int lane = t & 31, wid = t >> 5;
    int base = t * PER;

    int total = 0;
    for (int i = 0; i < PER; i++) {
        int n = base + i;
        if (n < N_NODES) total += g_cnt[n];
    }

    int v = total;
#pragma unroll
    for (int off = 1; off < 32; off <<= 1) {
        int u = __shfl_up_sync(0xffffffff, v, off);
        if (lane >= off) v += u;
    }
    if (lane == 31) warp_sums[wid] = v;
    __syncthreads();
    if (wid == 0) {
        int w = warp_sums[lane];
#pragma unroll
        for (int off = 1; off < 32; off <<= 1) {
            int u = __shfl_up_sync(0xffffffff, w, off);
            if (lane >= off) w += u;
        }
        warp_sums[lane] = w;
    }
    __syncthreads();
    int excl = v - total + (wid > 0 ? warp_sums[wid - 1] : 0);

    int run = excl;
    for (int i = 0; i < PER; i++) {
        int n = base + i;
        if (n < N_NODES) {
            g_off[n] = run;
            g_cursor[n] = run;
            int c = g_cnt[n];
            run += c;
            g_dinv[n] = rsqrtf((float)(c + 1));
        }
    }
    if (t == TPB - 1) g_off[N_NODES] = run;
}

__global__ void k_csr(const int* __restrict__ ei) {
    int e = blockIdx.x * blockDim.x + threadIdx.x;
    if (e < N_EDGES) {
        int src = ei[e];
        int dst = ei[N_EDGES + e];
        int pos = atomicAdd(&g_cursor[dst], 1);
        g_srcs[pos] = src;
    }
}

// ---------------------------------------------------------------------------
// x fp32 -> fp16 (padded rows zero-filled). One float4 -> 8B per thread.
// ---------------------------------------------------------------------------
__global__ __launch_bounds__(256) void k_cvt_x(const float* __restrict__ x) {
    const int TOT = N_PAD * IN_DIM / 4;
    int i = blockIdx.x * blockDim.x + threadIdx.x;
    if (i >= TOT) return;
    int row = i / (IN_DIM / 4);
    uint2 pk;
    if (row < N_NODES) {
        float4 v = ((const float4*)x)[i];
        __half2 h0 = __floats2half2_rn(v.x, v.y);
        __half2 h1 = __floats2half2_rn(v.z, v.w);
        pk.x = *(uint32_t*)&h0;
        pk.y = *(uint32_t*)&h1;
    } else {
        pk = make_uint2(0u, 0u);
    }
    ((uint2*)g_x2)[i] = pk;
}

// ---------------------------------------------------------------------------
// HMMA GEMM: h = x @ W via wmma 16x16x16 fp16 x fp16 + fp32 acc.
// CTA = 128 threads (4 warps), each warp computes a 16x128 strip.
// W (fp32) converted to fp16 in smem, one 128-k phase at a time (32 KB).
// ---------------------------------------------------------------------------
__global__ __launch_bounds__(128) void k_gemm_hmma(const float* __restrict__ W) {
    __shared__ __half Ws[128][128];   // 32 KB; aliased as fp32 staging on exit

    const int warp = threadIdx.x >> 5;
    const int row0 = blockIdx.x * 64 + warp * 16;

    wmma::fragment<wmma::accumulator, 16, 16, 16, float> accf[8];
#pragma unroll
    for (int nf = 0; nf < 8; nf++) wmma::fill_fragment(accf[nf], 0.0f);

#pragma unroll
    for (int phase = 0; phase < 2; phase++) {
        // load W[phase*128 .. +128][0..128] fp32 -> fp16 smem
        for (int idx = threadIdx.x; idx < 128 * 128 / 4; idx += 128) {
            int r = idx / 32;            // k-row within phase
            int c4 = idx % 32;           // float4 col group
            float4 v = *(const float4*)&W[(size_t)(phase * 128 + r) * OUT_DIM + c4 * 4];
            __half2 h0 = __floats2half2_rn(v.x, v.y);
            __half2 h1 = __floats2half2_rn(v.z, v.w);
            uint2 pk;
            pk.x = *(uint32_t*)&h0;
            pk.y = *(uint32_t*)&h1;
            *(uint2*)&Ws[r][c4 * 4] = pk;
        }
        __syncthreads();

#pragma unroll
        for (int ks = 0; ks < 8; ks++) {
            wmma::fragment<wmma::matrix_a, 16, 16, 16, __half, wmma::row_major> a;
            wmma::load_matrix_sync(a, g_x2 + (size_t)row0 * IN_DIM + phase * 128 + ks * 16, IN_DIM);
#pragma unroll
            for (int nf = 0; nf < 8; nf++) {
                wmma::fragment<wmma::matrix_b, 16, 16, 16, __half, wmma::row_major> b;
                wmma::load_matrix_sync(b, &Ws[ks * 16][nf * 16], 128);
                wmma::mma_sync(accf[nf], a, b, accf[nf]);
            }
        }
        __syncthreads();
    }

    // stage fp32 acc into smem (alias Ws: 64x128 floats = 32 KB), pack to fp16
    float* Hs = reinterpret_cast<float*>(&Ws[0][0]);
#pragma unroll
    for (int nf = 0; nf < 8; nf++)
        wmma::store_matrix_sync(Hs + (size_t)(warp * 16) * 128 + nf * 16,
                                accf[nf], 128, wmma::mem_row_major);
    __syncthreads();

    for (int v = threadIdx.x; v < 64 * 128 / 8; v += 128) {
        int base = v * 8;
        const float* p = Hs + base;
        __half2 a0 = __floats2half2_rn(p[0], p[1]);
        __half2 a1 = __floats2half2_rn(p[2], p[3]);
        __half2 a2 = __floats2half2_rn(p[4], p[5]);
        __half2 a3 = __floats2half2_rn(p[6], p[7]);
        uint4 pk;
        pk.x = *(uint32_t*)&a0; pk.y = *(uint32_t*)&a1;
        pk.z = *(uint32_t*)&a2; pk.w = *(uint32_t*)&a3;
        int grow = blockIdx.x * 64 + base / 128;
        int gcol = base % 128;
        *(uint4*)&g_h2[(size_t)grow * OUT_DIM + gcol] = pk;
    }
}

// ---------------------------------------------------------------------------
// Fused CSR gather (fp16 h) + spiking scan.
// One warp per dst node; HALF-warp per edge (16 lanes x 16B = 256B row).
// ---------------------------------------------------------------------------
__global__ __launch_bounds__(256) void k_gather_scan(float4* __restrict__ out) {
    int node = (blockIdx.x * 256 + threadIdx.x) >> 5;
    int lane = threadIdx.x & 31;
    if (node >= N_NODES) return;

    const int l16 = lane & 15;
    const int sel = lane >> 4;

    float di = g_dinv[node];
    float acc[8];
#pragma unroll
    for (int k = 0; k < 8; k++) acc[k] = 0.0f;

    if (sel == 0) {
        uint4 v = *(const uint4*)&g_h2[(size_t)node * OUT_DIM + l16 * 8];
        const __half2* hp = (const __half2*)&v;
        float di2 = di * di;
#pragma unroll
        for (int q = 0; q < 4; q++) {
            float2 f = __half22float2(hp[q]);
            acc[2 * q + 0] = f.x * di2;
            acc[2 * q + 1] = f.y * di2;
        }
    }

    int beg = g_off[node];
    int end = g_off[node + 1];

    for (int base = beg; base < end; base += 32) {
        int cnt = end - base;
        if (cnt > 32) cnt = 32;

        int   myidx = 0;
        float mynrm = 0.0f;
        if (lane < cnt) {
            myidx = g_srcs[base + lane];
            mynrm = g_dinv[myidx] * di;
        }

        int j = 0;
        for (; j + 8 <= cnt; j += 8) {
#pragma unroll
            for (int p = 0; p < 4; p++) {
                int   s  = __shfl_sync(0xffffffffu, myidx, j + 2 * p + sel);
                float nr = __shfl_sync(0xffffffffu, mynrm, j + 2 * p + sel);
                uint4 v = *(const uint4*)&g_h2[(size_t)s * OUT_DIM + l16 * 8];
                const __half2* hp = (const __half2*)&v;
#pragma unroll
                for (int q = 0; q < 4; q++) {
                    float2 f = __half22float2(hp[q]);
                    acc[2 * q + 0] += f.x * nr;
                    acc[2 * q + 1] += f.y * nr;
                }
            }
        }
        for (; j + 2 <= cnt; j += 2) {
            int   s  = __shfl_sync(0xffffffffu, myidx, j + sel);
            float nr = __shfl_sync(0xffffffffu, mynrm, j + sel);
            uint4 v = *(const uint4*)&g_h2[(size_t)s * OUT_DIM + l16 * 8];
            const __half2* hp = (const __half2*)&v;
#pragma unroll
            for (int q = 0; q < 4; q++) {
                float2 f = __half22float2(hp[q]);
                acc[2 * q + 0] += f.x * nr;
                acc[2 * q + 1] += f.y * nr;
            }
        }
        if (j < cnt) {
            int   s  = __shfl_sync(0xffffffffu, myidx, j);
            float nr = __shfl_sync(0xffffffffu, mynrm, j);
            if (sel == 0) {
                uint4 v = *(const uint4*)&g_h2[(size_t)s * OUT_DIM + l16 * 8];
                const __half2* hp = (const __half2*)&v;
#pragma unroll
                for (int q = 0; q < 4; q++) {
                    float2 f = __half22float2(hp[q]);
                    acc[2 * q + 0] += f.x * nr;
                    acc[2 * q + 1] += f.y * nr;
                }
            }
        }
    }

#pragma unroll
    for (int k = 0; k < 8; k++)
        acc[k] += __shfl_xor_sync(0xffffffffu, acc[k], 16);

    const int VEC = N_NODES * OUT_DIM / 4;
    int i = node * 32 + l16 * 2 + sel;
    int b = 4 * sel;
    float4 u = make_float4(acc[b + 0] * 0.1f, acc[b + 1] * 0.1f,
                           acc[b + 2] * 0.1f, acc[b + 3] * 0.1f);
    float4 z = make_float4(0.f, 0.f, 0.f, 0.f);

#pragma unroll
    for (int t = 0; t < T_STEPS; t++) {
        float4 Hm = make_float4(z.x + (u.x - z.x) * 0.5f,
                                z.y + (u.y - z.y) * 0.5f,
                                z.z + (u.z - z.z) * 0.5f,
                                z.w + (u.w - z.w) * 0.5f);
        float4 o = make_float4(Hm.x >= 1.0f ? 1.f : 0.f,
                               Hm.y >= 1.0f ? 1.f : 0.f,
                               Hm.z >= 1.0f ? 1.f : 0.f,
                               Hm.w >= 1.0f ? 1.f : 0.f);
        z = make_float4(Hm.x - o.x, Hm.y - o.y, Hm.z - o.z, Hm.w - o.w);
        __stcs(&out[(size_t)t * VEC + i], o);
        __stcs(&out[(size_t)(T_STEPS + t) * VEC + i], z);
    }
}

// ---------------------------------------------------------------------------
static cudaStream_t s_side = nullptr;
static cudaEvent_t  s_ev_fork = nullptr, s_ev_join = nullptr;

extern "C" void kernel_launch(void* const* d_in, const int* in_sizes, int n_in,
                              void* d_out, int out_size) {
    const float* x = (const float*)d_in[0];
    const float* W = (const float*)d_in[1];
    const int* ei = (const int*)d_in[2];
    float4* out = (float4*)d_out;

    if (s_side == nullptr) {
        cudaStreamCreateWithFlags(&s_side, cudaStreamNonBlocking);
        cudaEventCreateWithFlags(&s_ev_fork, cudaEventDisableTiming);
        cudaEventCreateWithFlags(&s_ev_join, cudaEventDisableTiming);
    }

    cudaEventRecord(s_ev_fork, 0);
    cudaStreamWaitEvent(s_side, s_ev_fork, 0);

    // side stream: CSR build chain
    k_zero_cnt<<<(N_NODES + 255) / 256, 256, 0, s_side>>>();
    k_hist<<<(N_EDGES + 255) / 256, 256, 0, s_side>>>(ei);
    k_offsets<<<1, 1024, 0, s_side>>>();
    k_csr<<<(N_EDGES + 255) / 256, 256, 0, s_side>>>(ei);
    cudaEventRecord(s_ev_join, s_side);

    // main stream: fp16 convert + tensor-core GEMM
    k_cvt_x<<<(N_PAD * IN_DIM / 4 + 255) / 256, 256>>>(x);
    k_gemm_hmma<<<N_PAD / 64, 128>>>(W);

    cudaStreamWaitEvent(0, s_ev_join, 0);
    k_gather_scan<<<(N_NODES * 32 + 255) / 256, 256>>>(out);
}